// round 1
// baseline (speedup 1.0000x reference)
#include <cuda_runtime.h>
#include <math.h>

// Problem constants
#define HIDDEN 2048
#define NHEAD  16
#define HDIM   128
#define BB     2
#define SSEQ   2048
#define BH     (BB * NHEAD)      // 32
#define MROWS  (BB * SSEQ)       // 4096

// GEMM tiling
#define BM  128
#define BN  128
#define BKK 16
#define TM  8
#define TN  8
// 256 threads per block: 16x16 thread grid, each thread 8x8 outputs.

// ---------------- scratch (device globals; no allocation allowed) -----------
__device__ __align__(128) float g_Q [(size_t)BH * SSEQ * HDIM];   // [B,H,S,D]
__device__ __align__(128) float g_K [(size_t)BH * SSEQ * HDIM];
__device__ __align__(128) float g_V [(size_t)BH * SSEQ * HDIM];
__device__ __align__(128) float g_P [(size_t)BH * SSEQ * SSEQ];   // scores/probs
__device__ __align__(128) float g_AO[(size_t)MROWS * HIDDEN];     // [B,S,HIDDEN]

// ---------------------------------------------------------------------------
// NT GEMM: C = alpha * A @ B^T (+bias). A:[M,K] row-major, B:[N,K] row-major.
// Optional batch via blockIdx.z with element strides. Requires M%128==0,
// N%128==0, K%16==0 (true for all uses here).
// out_mode 0: plain row-major C[m*N+n] (at C + z*cStrideZ)
// out_mode 1: QKV scatter into [B,H,S,D]  (m = b*S+s, n = h*D+d)
// ---------------------------------------------------------------------------
__global__ __launch_bounds__(256, 2)
void sgemm_nt(const float* __restrict__ A, long long aStrideZ,
              const float* __restrict__ B, long long bStrideZ,
              const float* __restrict__ bias,
              float* __restrict__ C, long long cStrideZ,
              int M, int N, int K, float alpha, int out_mode)
{
    __shared__ float As[BKK][BM];
    __shared__ float Bs[BKK][BN];

    const int z   = blockIdx.z;
    const float* Ap = A + (size_t)z * aStrideZ + (size_t)blockIdx.y * BM * K;
    const float* Bp = B + (size_t)z * bStrideZ + (size_t)blockIdx.x * BN * K;

    const int tid  = threadIdx.x;
    const int lrow = tid >> 2;          // 0..63
    const int lcol = (tid & 3) << 2;    // 0,4,8,12
    const int ty   = tid >> 4;          // 0..15
    const int tx   = tid & 15;          // 0..15

    float acc[TM][TN];
    #pragma unroll
    for (int i = 0; i < TM; i++)
        #pragma unroll
        for (int j = 0; j < TN; j++) acc[i][j] = 0.0f;

    for (int k0 = 0; k0 < K; k0 += BKK) {
        #pragma unroll
        for (int r = 0; r < 2; r++) {
            const int row = lrow + r * 64;
            float4 va = *reinterpret_cast<const float4*>(Ap + (size_t)row * K + k0 + lcol);
            As[lcol + 0][row] = va.x;
            As[lcol + 1][row] = va.y;
            As[lcol + 2][row] = va.z;
            As[lcol + 3][row] = va.w;
            float4 vb = *reinterpret_cast<const float4*>(Bp + (size_t)row * K + k0 + lcol);
            Bs[lcol + 0][row] = vb.x;
            Bs[lcol + 1][row] = vb.y;
            Bs[lcol + 2][row] = vb.z;
            Bs[lcol + 3][row] = vb.w;
        }
        __syncthreads();

        #pragma unroll
        for (int k = 0; k < BKK; k++) {
            float a[TM], b[TN];
            float4 a0 = *reinterpret_cast<const float4*>(&As[k][ty * TM]);
            float4 a1 = *reinterpret_cast<const float4*>(&As[k][ty * TM + 4]);
            float4 b0 = *reinterpret_cast<const float4*>(&Bs[k][tx * TN]);
            float4 b1 = *reinterpret_cast<const float4*>(&Bs[k][tx * TN + 4]);
            a[0]=a0.x; a[1]=a0.y; a[2]=a0.z; a[3]=a0.w;
            a[4]=a1.x; a[5]=a1.y; a[6]=a1.z; a[7]=a1.w;
            b[0]=b0.x; b[1]=b0.y; b[2]=b0.z; b[3]=b0.w;
            b[4]=b1.x; b[5]=b1.y; b[6]=b1.z; b[7]=b1.w;
            #pragma unroll
            for (int i = 0; i < TM; i++)
                #pragma unroll
                for (int j = 0; j < TN; j++)
                    acc[i][j] = fmaf(a[i], b[j], acc[i][j]);
        }
        __syncthreads();
    }

    // epilogue
    #pragma unroll
    for (int i = 0; i < TM; i++) {
        const int m = blockIdx.y * BM + ty * TM + i;
        #pragma unroll
        for (int j = 0; j < TN; j++) {
            const int n = blockIdx.x * BN + tx * TN + j;
            float v = acc[i][j] * alpha;
            if (bias) v += bias[n];
            if (out_mode == 0) {
                C[(size_t)z * cStrideZ + (size_t)m * N + n] = v;
            } else {
                // scatter into [B, H, S, D]
                const int b = m >> 11;          // m / SSEQ
                const int s = m & (SSEQ - 1);
                const int h = n >> 7;           // n / HDIM
                const int d = n & (HDIM - 1);
                C[(((size_t)(b * NHEAD + h) * SSEQ) + s) * HDIM + d] = v;
            }
        }
    }
}

// ---------------------------------------------------------------------------
// Row softmax over scores (adds additive mask per key position).
// grid: (SSEQ, BH), block: 256. Each thread handles 8 strided elements.
// ---------------------------------------------------------------------------
__global__ __launch_bounds__(256)
void softmax_kernel(float* __restrict__ P, const float* __restrict__ mask)
{
    const int q = blockIdx.x;
    const int z = blockIdx.y;
    const int b = z >> 4;   // z / NHEAD

    float* row = P + ((size_t)z * SSEQ + q) * SSEQ;
    const float* mrow = mask + (size_t)b * SSEQ;

    const int tid = threadIdx.x;
    float v[8];
    float mx = -1e30f;
    #pragma unroll
    for (int j = 0; j < 8; j++) {
        const int i = tid + j * 256;
        v[j] = row[i] + mrow[i];
        mx = fmaxf(mx, v[j]);
    }

    __shared__ float red[256];
    red[tid] = mx;
    __syncthreads();
    #pragma unroll
    for (int s = 128; s > 0; s >>= 1) {
        if (tid < s) red[tid] = fmaxf(red[tid], red[tid + s]);
        __syncthreads();
    }
    mx = red[0];
    __syncthreads();

    float sum = 0.0f;
    #pragma unroll
    for (int j = 0; j < 8; j++) {
        v[j] = __expf(v[j] - mx);
        sum += v[j];
    }
    red[tid] = sum;
    __syncthreads();
    #pragma unroll
    for (int s = 128; s > 0; s >>= 1) {
        if (tid < s) red[tid] += red[tid + s];
        __syncthreads();
    }
    const float inv = 1.0f / red[0];

    #pragma unroll
    for (int j = 0; j < 8; j++)
        row[tid + j * 256] = v[j] * inv;
}

// ---------------------------------------------------------------------------
// NN GEMM for P @ V, batched over heads. A = P[z]: [S,S], B = V[z]: [S,D].
// N == HDIM == 128 == BN (single N-tile). Scatters into [B,S,HIDDEN].
// ---------------------------------------------------------------------------
__global__ __launch_bounds__(256, 2)
void sgemm_nn_pv(const float* __restrict__ P, const float* __restrict__ V,
                 float* __restrict__ AO)
{
    __shared__ float As[BKK][BM];
    __shared__ float Bs[BKK][BN];

    const int z = blockIdx.z;
    const float* Ap = P + (size_t)z * SSEQ * SSEQ + (size_t)blockIdx.y * BM * SSEQ;
    const float* Bp = V + (size_t)z * SSEQ * HDIM;

    const int tid  = threadIdx.x;
    const int lrow = tid >> 2;          // A loader: 0..63
    const int lcol = (tid & 3) << 2;
    const int ty   = tid >> 4;
    const int tx   = tid & 15;

    float acc[TM][TN];
    #pragma unroll
    for (int i = 0; i < TM; i++)
        #pragma unroll
        for (int j = 0; j < TN; j++) acc[i][j] = 0.0f;

    for (int k0 = 0; k0 < SSEQ; k0 += BKK) {
        // A tile (transpose to As[k][m])
        #pragma unroll
        for (int r = 0; r < 2; r++) {
            const int row = lrow + r * 64;
            float4 va = *reinterpret_cast<const float4*>(Ap + (size_t)row * SSEQ + k0 + lcol);
            As[lcol + 0][row] = va.x;
            As[lcol + 1][row] = va.y;
            As[lcol + 2][row] = va.z;
            As[lcol + 3][row] = va.w;
        }
        // B tile (natural layout Bs[k][n])
        #pragma unroll
        for (int r = 0; r < 2; r++) {
            const int idx = tid + r * 256;
            const int kr  = idx >> 5;            // 0..15
            const int c4  = (idx & 31) << 2;     // 0..124
            float4 vb = *reinterpret_cast<const float4*>(Bp + (size_t)(k0 + kr) * HDIM + c4);
            *reinterpret_cast<float4*>(&Bs[kr][c4]) = vb;
        }
        __syncthreads();

        #pragma unroll
        for (int k = 0; k < BKK; k++) {
            float a[TM], b[TN];
            float4 a0 = *reinterpret_cast<const float4*>(&As[k][ty * TM]);
            float4 a1 = *reinterpret_cast<const float4*>(&As[k][ty * TM + 4]);
            float4 b0 = *reinterpret_cast<const float4*>(&Bs[k][tx * TN]);
            float4 b1 = *reinterpret_cast<const float4*>(&Bs[k][tx * TN + 4]);
            a[0]=a0.x; a[1]=a0.y; a[2]=a0.z; a[3]=a0.w;
            a[4]=a1.x; a[5]=a1.y; a[6]=a1.z; a[7]=a1.w;
            b[0]=b0.x; b[1]=b0.y; b[2]=b0.z; b[3]=b0.w;
            b[4]=b1.x; b[5]=b1.y; b[6]=b1.z; b[7]=b1.w;
            #pragma unroll
            for (int i = 0; i < TM; i++)
                #pragma unroll
                for (int j = 0; j < TN; j++)
                    acc[i][j] = fmaf(a[i], b[j], acc[i][j]);
        }
        __syncthreads();
    }

    const int b = z >> 4;
    const int h = z & (NHEAD - 1);
    #pragma unroll
    for (int i = 0; i < TM; i++) {
        const int m = blockIdx.y * BM + ty * TM + i;   // query index s
        #pragma unroll
        for (int j = 0; j < TN; j++) {
            const int n = tx * TN + j;                  // head dim d
            AO[((size_t)(b * SSEQ + m)) * HIDDEN + h * HDIM + n] = acc[i][j];
        }
    }
}

// ---------------------------------------------------------------------------
extern "C" void kernel_launch(void* const* d_in, const int* in_sizes, int n_in,
                              void* d_out, int out_size)
{
    (void)in_sizes; (void)n_in; (void)out_size;
    const float* x    = (const float*)d_in[0];
    const float* mask = (const float*)d_in[1];
    const float* Wq   = (const float*)d_in[2];
    const float* bq   = (const float*)d_in[3];
    const float* Wk   = (const float*)d_in[4];
    const float* bk   = (const float*)d_in[5];
    const float* Wv   = (const float*)d_in[6];
    const float* bv   = (const float*)d_in[7];
    const float* Wo   = (const float*)d_in[8];
    const float* bo   = (const float*)d_in[9];
    float* out = (float*)d_out;

    float *Qg, *Kg, *Vg, *Pg, *AOg;
    cudaGetSymbolAddress((void**)&Qg,  g_Q);
    cudaGetSymbolAddress((void**)&Kg,  g_K);
    cudaGetSymbolAddress((void**)&Vg,  g_V);
    cudaGetSymbolAddress((void**)&Pg,  g_P);
    cudaGetSymbolAddress((void**)&AOg, g_AO);

    const dim3 blk(256);

    // QKV projections: [4096,2048] @ W^T -> scatter to [B,H,S,D]
    const dim3 gProj(HIDDEN / BN, MROWS / BM, 1);
    sgemm_nt<<<gProj, blk>>>(x, 0, Wq, 0, bq, Qg, 0, MROWS, HIDDEN, HIDDEN, 1.0f, 1);
    sgemm_nt<<<gProj, blk>>>(x, 0, Wk, 0, bk, Kg, 0, MROWS, HIDDEN, HIDDEN, 1.0f, 1);
    sgemm_nt<<<gProj, blk>>>(x, 0, Wv, 0, bv, Vg, 0, MROWS, HIDDEN, HIDDEN, 1.0f, 1);

    // Scores: per-head Q @ K^T * (1/sqrt(D))
    const float scale = 1.0f / sqrtf((float)HDIM);
    const dim3 gS(SSEQ / BN, SSEQ / BM, BH);
    sgemm_nt<<<gS, blk>>>(Qg, (long long)SSEQ * HDIM,
                          Kg, (long long)SSEQ * HDIM,
                          nullptr,
                          Pg, (long long)SSEQ * SSEQ,
                          SSEQ, SSEQ, HDIM, scale, 0);

    // Softmax (adds additive mask)
    const dim3 gSm(SSEQ, BH);
    softmax_kernel<<<gSm, blk>>>(Pg, mask);

    // P @ V -> scatter into [B,S,HIDDEN]
    const dim3 gPV(1, SSEQ / BM, BH);
    sgemm_nn_pv<<<gPV, blk>>>(Pg, Vg, AOg);

    // Output projection (+bias) -> d_out
    const dim3 gO(HIDDEN / BN, MROWS / BM, 1);
    sgemm_nt<<<gO, blk>>>(AOg, 0, Wo, 0, bo, out, 0, MROWS, HIDDEN, HIDDEN, 1.0f, 0);
}

// round 3
// speedup vs baseline: 2.5917x; 2.5917x over previous
#include <cuda_runtime.h>
#include <cuda_bf16.h>
#include <math.h>
#include <stdint.h>

// Problem constants
#define HIDDEN 2048
#define NHEAD  16
#define HDIM   128
#define BB     2
#define SSEQ   2048
#define BH     (BB * NHEAD)      // 32
#define MROWS  (BB * SSEQ)       // 4096

// ---------------- scratch (device globals; no allocation allowed) -----------
__device__ __align__(128) float g_P [(size_t)BH * SSEQ * SSEQ];   // fp32 scores

__device__ __align__(128) __nv_bfloat16 g_xh [(size_t)MROWS * HIDDEN];
__device__ __align__(128) __nv_bfloat16 g_xl [(size_t)MROWS * HIDDEN];
__device__ __align__(128) __nv_bfloat16 g_wqh[(size_t)HIDDEN * HIDDEN];
__device__ __align__(128) __nv_bfloat16 g_wql[(size_t)HIDDEN * HIDDEN];
__device__ __align__(128) __nv_bfloat16 g_wkh[(size_t)HIDDEN * HIDDEN];
__device__ __align__(128) __nv_bfloat16 g_wkl[(size_t)HIDDEN * HIDDEN];
__device__ __align__(128) __nv_bfloat16 g_wvh[(size_t)HIDDEN * HIDDEN];
__device__ __align__(128) __nv_bfloat16 g_wvl[(size_t)HIDDEN * HIDDEN];
__device__ __align__(128) __nv_bfloat16 g_woh[(size_t)HIDDEN * HIDDEN];
__device__ __align__(128) __nv_bfloat16 g_wol[(size_t)HIDDEN * HIDDEN];
__device__ __align__(128) __nv_bfloat16 g_qh [(size_t)BH * SSEQ * HDIM];  // [B,H,S,D]
__device__ __align__(128) __nv_bfloat16 g_ql [(size_t)BH * SSEQ * HDIM];
__device__ __align__(128) __nv_bfloat16 g_kh [(size_t)BH * SSEQ * HDIM];
__device__ __align__(128) __nv_bfloat16 g_kl [(size_t)BH * SSEQ * HDIM];
__device__ __align__(128) __nv_bfloat16 g_vth[(size_t)BH * HDIM * SSEQ];  // [B,H,D,S]
__device__ __align__(128) __nv_bfloat16 g_vtl[(size_t)BH * HDIM * SSEQ];
__device__ __align__(128) __nv_bfloat16 g_ph [(size_t)BH * SSEQ * SSEQ];  // probs hi
__device__ __align__(128) __nv_bfloat16 g_pl [(size_t)BH * SSEQ * SSEQ];  // probs lo
__device__ __align__(128) __nv_bfloat16 g_aoh[(size_t)MROWS * HIDDEN];
__device__ __align__(128) __nv_bfloat16 g_aol[(size_t)MROWS * HIDDEN];

// ============================ PTX helpers ====================================
__device__ __forceinline__ uint32_t smem_to_u32(const void* smem_ptr) {
    uint32_t addr;
    asm("{ .reg .u64 tmp; cvta.to.shared.u64 tmp, %1; cvt.u32.u64 %0, tmp; }"
        : "=r"(addr) : "l"(smem_ptr));
    return addr;
}
#define CP_ASYNC16(smem_u32, gptr) \
    asm volatile("cp.async.cg.shared.global [%0], [%1], 16;" \
        :: "r"((uint32_t)(smem_u32)), "l"(gptr) : "memory")
#define CP_ASYNC_COMMIT() asm volatile("cp.async.commit_group;" ::: "memory")
#define CP_ASYNC_WAIT(n)  asm volatile("cp.async.wait_group %0;" :: "n"(n) : "memory")

__device__ __forceinline__ void ldsm4(uint32_t* r, uint32_t addr) {
    asm volatile("ldmatrix.sync.aligned.m8n8.x4.shared.b16 {%0,%1,%2,%3}, [%4];"
        : "=r"(r[0]), "=r"(r[1]), "=r"(r[2]), "=r"(r[3]) : "r"(addr));
}
__device__ __forceinline__ void mma16816(float* d, const uint32_t* a,
                                         uint32_t b0, uint32_t b1) {
    asm volatile(
        "mma.sync.aligned.m16n8k16.row.col.f32.bf16.bf16.f32 "
        "{%0,%1,%2,%3}, {%4,%5,%6,%7}, {%8,%9}, {%0,%1,%2,%3};"
        : "+f"(d[0]), "+f"(d[1]), "+f"(d[2]), "+f"(d[3])
        : "r"(a[0]), "r"(a[1]), "r"(a[2]), "r"(a[3]), "r"(b0), "r"(b1));
}

// ===================== HMMA bf16x3 NT GEMM ==================================
// C = alpha * (Ah+Al) @ (Bh+Bl)^T (+bias).   A*: [M,K] bf16 row-major,
// B*: [Ntot,K] bf16 row-major.  Tiles: CTA 128x128, warp 64x32, K-chunk 64.
// Products kept: AhBh + AlBh + AhBl  (drop AlBl, ~2^-18).
// Modes (epilogue):
//  0: fp32 C[m*2048+n]                       (O projection -> d_out)
//  1: bf16 hi/lo scatter [B,H,S,D]           (Q, K)
//  2: bf16 hi/lo scatter [B,H,D,S] (V^T)     (V)
//  3: fp32 P[z][m][n] batched, scaled        (scores)
//  4: bf16 hi/lo AO [(b*S+m)*HIDDEN+h*128+n] (PV)
#define TG_STRIDE   144                       // padded row bytes (64 bf16 + 8 pad)
#define TG_TILE     (128 * TG_STRIDE)         // 18432 B
#define TG_STAGE    (4 * TG_TILE)             // Ah, Al, Bh, Bl
#define TG_SMEM     (2 * TG_STAGE)            // 147456 B

__global__ void __launch_bounds__(256, 1)
tgemm_nt(const __nv_bfloat16* __restrict__ Ah, const __nv_bfloat16* __restrict__ Al,
         const __nv_bfloat16* __restrict__ Bh, const __nv_bfloat16* __restrict__ Bl,
         long long aZ, long long bZ,
         const float* __restrict__ bias, int K, float alpha, int mode,
         float* __restrict__ outF,
         __nv_bfloat16* __restrict__ outH, __nv_bfloat16* __restrict__ outL)
{
    extern __shared__ __align__(128) char smem[];
    const uint32_t sb = smem_to_u32(smem);

    const int tid  = threadIdx.x;
    const int lane = tid & 31;
    const int wid  = tid >> 5;
    const int wm   = wid >> 2;        // 0..1
    const int wn   = wid & 3;         // 0..3

    const int z  = blockIdx.z;
    const int m0 = blockIdx.y * 128;
    const int n0 = blockIdx.x * 128;
    const int nch = K >> 6;

    const size_t aBase = (size_t)z * aZ + (size_t)m0 * K;
    const size_t bBase = (size_t)z * bZ + (size_t)n0 * K;

    float acc[4][4][4];
    #pragma unroll
    for (int i = 0; i < 4; i++)
        #pragma unroll
        for (int j = 0; j < 4; j++)
            #pragma unroll
            for (int t = 0; t < 4; t++) acc[i][j][t] = 0.0f;

    // ---- loader: per stage 4 tiles of [128 rows x 64 bf16], row stride 144B
    auto load_chunk = [&](int buf, int k0) {
        const uint32_t tb = sb + buf * TG_STAGE;
        #pragma unroll
        for (int ii = 0; ii < 4; ii++) {
            const int i = tid + ii * 256;        // 0..1023
            const int r = i >> 3;                // row 0..127
            const int c = i & 7;                 // 16B chunk 0..7
            const uint32_t so = (uint32_t)(r * TG_STRIDE + c * 16);
            const size_t aOff = aBase + (size_t)r * K + k0 + c * 8;
            const size_t bOff = bBase + (size_t)r * K + k0 + c * 8;
            CP_ASYNC16(tb + 0 * TG_TILE + so, (const char*)(Ah + aOff));
            CP_ASYNC16(tb + 1 * TG_TILE + so, (const char*)(Al + aOff));
            CP_ASYNC16(tb + 2 * TG_TILE + so, (const char*)(Bh + bOff));
            CP_ASYNC16(tb + 3 * TG_TILE + so, (const char*)(Bl + bOff));
        }
        CP_ASYNC_COMMIT();
    };

    // lane-dependent ldmatrix offsets (bytes within a tile)
    const uint32_t aOffL = (uint32_t)((wm * 64 + (lane & 15)) * TG_STRIDE
                                      + ((lane >> 4) * 8) * 2);
    const uint32_t bOffL = (uint32_t)((wn * 32 + (lane & 7) + ((lane >> 4) & 1) * 8) * TG_STRIDE
                                      + (((lane >> 3) & 1) * 8) * 2);

    load_chunk(0, 0);
    load_chunk(1, 64);

    for (int c = 0; c < nch; c++) {
        const int buf = c & 1;
        if (c + 1 < nch) { CP_ASYNC_WAIT(1); } else { CP_ASYNC_WAIT(0); }
        __syncthreads();

        const uint32_t tb  = sb + buf * TG_STAGE;
        const uint32_t tAh = tb + 0 * TG_TILE + aOffL;
        const uint32_t tAl = tb + 1 * TG_TILE + aOffL;
        const uint32_t tBh = tb + 2 * TG_TILE + bOffL;
        const uint32_t tBl = tb + 3 * TG_TILE + bOffL;

        #pragma unroll
        for (int ks = 0; ks < 4; ks++) {
            const uint32_t ko = ks * 32;   // 16 bf16 = 32B
            uint32_t ah[4][4], al[4][4], bh[2][4], bl[2][4];
            #pragma unroll
            for (int mt = 0; mt < 4; mt++) {
                ldsm4(ah[mt], tAh + mt * (16 * TG_STRIDE) + ko);
                ldsm4(al[mt], tAl + mt * (16 * TG_STRIDE) + ko);
            }
            #pragma unroll
            for (int nt = 0; nt < 2; nt++) {
                ldsm4(bh[nt], tBh + nt * (16 * TG_STRIDE) + ko);
                ldsm4(bl[nt], tBl + nt * (16 * TG_STRIDE) + ko);
            }
            #pragma unroll
            for (int mi = 0; mi < 4; mi++)
                #pragma unroll
                for (int ni = 0; ni < 4; ni++) {
                    const int g = ni >> 1, o = (ni & 1) * 2;
                    mma16816(acc[mi][ni], ah[mi], bh[g][o], bh[g][o + 1]); // Ah*Bh
                    mma16816(acc[mi][ni], al[mi], bh[g][o], bh[g][o + 1]); // Al*Bh
                    mma16816(acc[mi][ni], ah[mi], bl[g][o], bl[g][o + 1]); // Ah*Bl
                }
        }
        __syncthreads();
        if (c + 2 < nch) load_chunk(buf, (c + 2) * 64);
    }

    // ---------------- epilogue ----------------
    const int gid = lane >> 2;   // 0..7
    const int tig = lane & 3;    // 0..3

    auto storePair = [&](int m, int n, float v0, float v1) {
        v0 *= alpha; v1 *= alpha;
        if (bias) { v0 += bias[n]; v1 += bias[n + 1]; }
        if (mode == 0) {
            float2 t; t.x = v0; t.y = v1;
            *reinterpret_cast<float2*>(&outF[(size_t)m * 2048 + n]) = t;
        } else if (mode == 3) {
            float2 t; t.x = v0; t.y = v1;
            *reinterpret_cast<float2*>(
                &outF[(size_t)z * SSEQ * SSEQ + (size_t)m * SSEQ + n]) = t;
        } else {
            __nv_bfloat16 h0 = __float2bfloat16(v0);
            __nv_bfloat16 l0 = __float2bfloat16(v0 - __bfloat162float(h0));
            __nv_bfloat16 h1 = __float2bfloat16(v1);
            __nv_bfloat16 l1 = __float2bfloat16(v1 - __bfloat162float(h1));
            if (mode == 1) {
                const int b = m >> 11, s = m & (SSEQ - 1);
                const int h = n >> 7,  d = n & (HDIM - 1);
                const size_t idx = (((size_t)(b * NHEAD + h) * SSEQ) + s) * HDIM + d;
                __nv_bfloat162 th; th.x = h0; th.y = h1;
                __nv_bfloat162 tl; tl.x = l0; tl.y = l1;
                *reinterpret_cast<__nv_bfloat162*>(&outH[idx]) = th;
                *reinterpret_cast<__nv_bfloat162*>(&outL[idx]) = tl;
            } else if (mode == 2) {
                const int b = m >> 11, s = m & (SSEQ - 1);
                const int h = n >> 7,  d = n & (HDIM - 1);
                const size_t idx = (((size_t)(b * NHEAD + h) * HDIM) + d) * SSEQ + s;
                outH[idx] = h0; outH[idx + SSEQ] = h1;
                outL[idx] = l0; outL[idx + SSEQ] = l1;
            } else { // mode 4
                const int b = z >> 4, h = z & (NHEAD - 1);
                const size_t idx = ((size_t)(b * SSEQ + m)) * HIDDEN + h * HDIM + n;
                __nv_bfloat162 th; th.x = h0; th.y = h1;
                __nv_bfloat162 tl; tl.x = l0; tl.y = l1;
                *reinterpret_cast<__nv_bfloat162*>(&outH[idx]) = th;
                *reinterpret_cast<__nv_bfloat162*>(&outL[idx]) = tl;
            }
        }
    };

    #pragma unroll
    for (int mi = 0; mi < 4; mi++) {
        #pragma unroll
        for (int ni = 0; ni < 4; ni++) {
            const int m = m0 + wm * 64 + mi * 16 + gid;
            const int n = n0 + wn * 32 + ni * 8 + tig * 2;
            storePair(m,     n, acc[mi][ni][0], acc[mi][ni][1]);
            storePair(m + 8, n, acc[mi][ni][2], acc[mi][ni][3]);
        }
    }
}

// ===================== fp32 -> bf16 hi/lo split =============================
__global__ void __launch_bounds__(256)
split_bf16(const float* __restrict__ in, __nv_bfloat16* __restrict__ hi,
           __nv_bfloat16* __restrict__ lo, int n4)
{
    const int i = blockIdx.x * 256 + threadIdx.x;
    if (i >= n4) return;
    const float4 v = reinterpret_cast<const float4*>(in)[i];
    union { __nv_bfloat16 b[4]; uint2 u; } H, L;
    H.b[0] = __float2bfloat16(v.x);
    H.b[1] = __float2bfloat16(v.y);
    H.b[2] = __float2bfloat16(v.z);
    H.b[3] = __float2bfloat16(v.w);
    L.b[0] = __float2bfloat16(v.x - __bfloat162float(H.b[0]));
    L.b[1] = __float2bfloat16(v.y - __bfloat162float(H.b[1]));
    L.b[2] = __float2bfloat16(v.z - __bfloat162float(H.b[2]));
    L.b[3] = __float2bfloat16(v.w - __bfloat162float(H.b[3]));
    reinterpret_cast<uint2*>(hi)[i] = H.u;
    reinterpret_cast<uint2*>(lo)[i] = L.u;
}

// ============================ softmax =======================================
// Reads fp32 scores, adds mask, softmax, writes bf16 hi/lo probs.
__global__ void __launch_bounds__(256)
softmax_kernel(const float* __restrict__ P, const float* __restrict__ mask,
               __nv_bfloat16* __restrict__ ph, __nv_bfloat16* __restrict__ pl)
{
    const int q = blockIdx.x;
    const int z = blockIdx.y;
    const int b = z >> 4;

    const size_t base = ((size_t)z * SSEQ + q) * SSEQ;
    const float* row  = P + base;
    const float* mrow = mask + (size_t)b * SSEQ;

    const int tid = threadIdx.x;
    float v[8];
    float mx = -1e30f;
    #pragma unroll
    for (int j = 0; j < 8; j++) {
        const int i = tid + j * 256;
        v[j] = row[i] + mrow[i];
        mx = fmaxf(mx, v[j]);
    }

    __shared__ float red[256];
    red[tid] = mx;
    __syncthreads();
    #pragma unroll
    for (int s = 128; s > 0; s >>= 1) {
        if (tid < s) red[tid] = fmaxf(red[tid], red[tid + s]);
        __syncthreads();
    }
    mx = red[0];
    __syncthreads();

    float sum = 0.0f;
    #pragma unroll
    for (int j = 0; j < 8; j++) {
        v[j] = __expf(v[j] - mx);
        sum += v[j];
    }
    red[tid] = sum;
    __syncthreads();
    #pragma unroll
    for (int s = 128; s > 0; s >>= 1) {
        if (tid < s) red[tid] += red[tid + s];
        __syncthreads();
    }
    const float inv = 1.0f / red[0];

    #pragma unroll
    for (int j = 0; j < 8; j++) {
        const float p = v[j] * inv;
        const __nv_bfloat16 h = __float2bfloat16(p);
        const __nv_bfloat16 l = __float2bfloat16(p - __bfloat162float(h));
        ph[base + tid + j * 256] = h;
        pl[base + tid + j * 256] = l;
    }
}

// ---------------------------------------------------------------------------
extern "C" void kernel_launch(void* const* d_in, const int* in_sizes, int n_in,
                              void* d_out, int out_size)
{
    (void)in_sizes; (void)n_in; (void)out_size;
    const float* x    = (const float*)d_in[0];
    const float* mask = (const float*)d_in[1];
    const float* Wq   = (const float*)d_in[2];
    const float* bq   = (const float*)d_in[3];
    const float* Wk   = (const float*)d_in[4];
    const float* bk   = (const float*)d_in[5];
    const float* Wv   = (const float*)d_in[6];
    const float* bv   = (const float*)d_in[7];
    const float* Wo   = (const float*)d_in[8];
    const float* bo   = (const float*)d_in[9];
    float* out = (float*)d_out;

    float* Pg;
    cudaGetSymbolAddress((void**)&Pg, g_P);
    __nv_bfloat16 *xh, *xl, *wqh, *wql, *wkh, *wkl, *wvh, *wvl, *woh, *wol;
    __nv_bfloat16 *qh, *ql, *kh, *kl, *vth, *vtl, *ph, *pl, *aoh, *aol;
    cudaGetSymbolAddress((void**)&xh,  g_xh);
    cudaGetSymbolAddress((void**)&xl,  g_xl);
    cudaGetSymbolAddress((void**)&wqh, g_wqh);
    cudaGetSymbolAddress((void**)&wql, g_wql);
    cudaGetSymbolAddress((void**)&wkh, g_wkh);
    cudaGetSymbolAddress((void**)&wkl, g_wkl);
    cudaGetSymbolAddress((void**)&wvh, g_wvh);
    cudaGetSymbolAddress((void**)&wvl, g_wvl);
    cudaGetSymbolAddress((void**)&woh, g_woh);
    cudaGetSymbolAddress((void**)&wol, g_wol);
    cudaGetSymbolAddress((void**)&qh,  g_qh);
    cudaGetSymbolAddress((void**)&ql,  g_ql);
    cudaGetSymbolAddress((void**)&kh,  g_kh);
    cudaGetSymbolAddress((void**)&kl,  g_kl);
    cudaGetSymbolAddress((void**)&vth, g_vth);
    cudaGetSymbolAddress((void**)&vtl, g_vtl);
    cudaGetSymbolAddress((void**)&ph,  g_ph);
    cudaGetSymbolAddress((void**)&pl,  g_pl);
    cudaGetSymbolAddress((void**)&aoh, g_aoh);
    cudaGetSymbolAddress((void**)&aol, g_aol);

    cudaFuncSetAttribute(tgemm_nt, cudaFuncAttributeMaxDynamicSharedMemorySize,
                         TG_SMEM);

    // ---- hi/lo splits of inputs
    const int nX4 = (MROWS * HIDDEN) / 4;
    const int nW4 = (HIDDEN * HIDDEN) / 4;
    split_bf16<<<nX4 / 256, 256>>>(x,  xh,  xl,  nX4);
    split_bf16<<<nW4 / 256, 256>>>(Wq, wqh, wql, nW4);
    split_bf16<<<nW4 / 256, 256>>>(Wk, wkh, wkl, nW4);
    split_bf16<<<nW4 / 256, 256>>>(Wv, wvh, wvl, nW4);
    split_bf16<<<nW4 / 256, 256>>>(Wo, woh, wol, nW4);

    // ---- projections
    const dim3 gProj(HIDDEN / 128, MROWS / 128, 1);   // (16, 32, 1)
    tgemm_nt<<<gProj, 256, TG_SMEM>>>(xh, xl, wqh, wql, 0, 0, bq, HIDDEN, 1.0f, 1,
                                      nullptr, qh, ql);
    tgemm_nt<<<gProj, 256, TG_SMEM>>>(xh, xl, wkh, wkl, 0, 0, bk, HIDDEN, 1.0f, 1,
                                      nullptr, kh, kl);
    tgemm_nt<<<gProj, 256, TG_SMEM>>>(xh, xl, wvh, wvl, 0, 0, bv, HIDDEN, 1.0f, 2,
                                      nullptr, vth, vtl);

    // ---- scores: per-head Q @ K^T * (1/sqrt(D))
    const float scale = 1.0f / sqrtf((float)HDIM);
    const dim3 gS(SSEQ / 128, SSEQ / 128, BH);        // (16, 16, 32)
    tgemm_nt<<<gS, 256, TG_SMEM>>>(qh, ql, kh, kl,
                                   (long long)SSEQ * HDIM, (long long)SSEQ * HDIM,
                                   nullptr, HDIM, scale, 3, Pg, nullptr, nullptr);

    // ---- softmax -> bf16 hi/lo probs
    const dim3 gSm(SSEQ, BH);
    softmax_kernel<<<gSm, 256>>>(Pg, mask, ph, pl);

    // ---- P @ V (via V^T, NT) -> AO bf16 hi/lo
    const dim3 gPV(HDIM / 128, SSEQ / 128, BH);       // (1, 16, 32)
    tgemm_nt<<<gPV, 256, TG_SMEM>>>(ph, pl, vth, vtl,
                                    (long long)SSEQ * SSEQ, (long long)HDIM * SSEQ,
                                    nullptr, SSEQ, 1.0f, 4, nullptr, aoh, aol);

    // ---- output projection (+bias) -> d_out
    tgemm_nt<<<gProj, 256, TG_SMEM>>>(aoh, aol, woh, wol, 0, 0, bo, HIDDEN, 1.0f, 0,
                                      out, nullptr, nullptr);
}

// round 4
// speedup vs baseline: 2.9968x; 1.1563x over previous
#include <cuda_runtime.h>
#include <cuda_bf16.h>
#include <math.h>
#include <stdint.h>

// Problem constants
#define HIDDEN 2048
#define NHEAD  16
#define HDIM   128
#define BB     2
#define SSEQ   2048
#define BH     (BB * NHEAD)      // 32
#define MROWS  (BB * SSEQ)       // 4096

// ---------------- scratch (device globals; no allocation allowed) -----------
__device__ __align__(128) __nv_bfloat16 g_xh [(size_t)MROWS * HIDDEN];
__device__ __align__(128) __nv_bfloat16 g_xl [(size_t)MROWS * HIDDEN];
__device__ __align__(128) __nv_bfloat16 g_wqh[(size_t)HIDDEN * HIDDEN];
__device__ __align__(128) __nv_bfloat16 g_wql[(size_t)HIDDEN * HIDDEN];
__device__ __align__(128) __nv_bfloat16 g_wkh[(size_t)HIDDEN * HIDDEN];
__device__ __align__(128) __nv_bfloat16 g_wkl[(size_t)HIDDEN * HIDDEN];
__device__ __align__(128) __nv_bfloat16 g_wvh[(size_t)HIDDEN * HIDDEN];
__device__ __align__(128) __nv_bfloat16 g_wvl[(size_t)HIDDEN * HIDDEN];
__device__ __align__(128) __nv_bfloat16 g_woh[(size_t)HIDDEN * HIDDEN];
__device__ __align__(128) __nv_bfloat16 g_wol[(size_t)HIDDEN * HIDDEN];
__device__ __align__(128) __nv_bfloat16 g_qh [(size_t)BH * SSEQ * HDIM];  // [B,H,S,D]
__device__ __align__(128) __nv_bfloat16 g_ql [(size_t)BH * SSEQ * HDIM];
__device__ __align__(128) __nv_bfloat16 g_kh [(size_t)BH * SSEQ * HDIM];
__device__ __align__(128) __nv_bfloat16 g_kl [(size_t)BH * SSEQ * HDIM];
__device__ __align__(128) __nv_bfloat16 g_vh [(size_t)BH * SSEQ * HDIM];
__device__ __align__(128) __nv_bfloat16 g_vl [(size_t)BH * SSEQ * HDIM];
__device__ __align__(128) __nv_bfloat16 g_aoh[(size_t)MROWS * HIDDEN];
__device__ __align__(128) __nv_bfloat16 g_aol[(size_t)MROWS * HIDDEN];

// ============================ PTX helpers ====================================
__device__ __forceinline__ uint32_t smem_to_u32(const void* smem_ptr) {
    uint32_t addr;
    asm("{ .reg .u64 tmp; cvta.to.shared.u64 tmp, %1; cvt.u32.u64 %0, tmp; }"
        : "=r"(addr) : "l"(smem_ptr));
    return addr;
}
#define CP_ASYNC16(smem_u32, gptr) \
    asm volatile("cp.async.cg.shared.global [%0], [%1], 16;" \
        :: "r"((uint32_t)(smem_u32)), "l"(gptr) : "memory")
#define CP_ASYNC_COMMIT() asm volatile("cp.async.commit_group;" ::: "memory")
#define CP_ASYNC_WAIT(n)  asm volatile("cp.async.wait_group %0;" :: "n"(n) : "memory")

__device__ __forceinline__ void ldsm4(uint32_t* r, uint32_t addr) {
    asm volatile("ldmatrix.sync.aligned.m8n8.x4.shared.b16 {%0,%1,%2,%3}, [%4];"
        : "=r"(r[0]), "=r"(r[1]), "=r"(r[2]), "=r"(r[3]) : "r"(addr));
}
__device__ __forceinline__ void ldsm4t(uint32_t* r, uint32_t addr) {
    asm volatile("ldmatrix.sync.aligned.m8n8.x4.trans.shared.b16 {%0,%1,%2,%3}, [%4];"
        : "=r"(r[0]), "=r"(r[1]), "=r"(r[2]), "=r"(r[3]) : "r"(addr));
}
__device__ __forceinline__ void mma16816(float* d, const uint32_t* a,
                                         uint32_t b0, uint32_t b1) {
    asm volatile(
        "mma.sync.aligned.m16n8k16.row.col.f32.bf16.bf16.f32 "
        "{%0,%1,%2,%3}, {%4,%5,%6,%7}, {%8,%9}, {%0,%1,%2,%3};"
        : "+f"(d[0]), "+f"(d[1]), "+f"(d[2]), "+f"(d[3])
        : "r"(a[0]), "r"(a[1]), "r"(a[2]), "r"(a[3]), "r"(b0), "r"(b1));
}
__device__ __forceinline__ uint32_t pack_bf16x2(float lo, float hi) {
    __nv_bfloat162 t;
    t.x = __float2bfloat16(lo);
    t.y = __float2bfloat16(hi);
    return *reinterpret_cast<uint32_t*>(&t);
}

// ===================== HMMA bf16x3 NT GEMM (projections) ====================
// C = (Ah+Al) @ (Bh+Bl)^T (+bias).  A*: [M,K] bf16 row-major, B*: [N,K].
// CTA tile 128x128, warp 64x32, K-chunk 64.  Kept products: AhBh+AlBh+AhBl.
// mode 0: fp32 C[m*2048+n]; mode 1: bf16 hi/lo scatter [B,H,S,D].
#define TG_STRIDE   144
#define TG_TILE     (128 * TG_STRIDE)
#define TG_STAGE    (4 * TG_TILE)
#define TG_SMEM     (2 * TG_STAGE)     // 147456

__global__ void __launch_bounds__(256, 1)
tgemm_nt(const __nv_bfloat16* __restrict__ Ah, const __nv_bfloat16* __restrict__ Al,
         const __nv_bfloat16* __restrict__ Bh, const __nv_bfloat16* __restrict__ Bl,
         const float* __restrict__ bias, int K, int mode,
         float* __restrict__ outF,
         __nv_bfloat16* __restrict__ outH, __nv_bfloat16* __restrict__ outL)
{
    extern __shared__ __align__(128) char smem[];
    const uint32_t sb = smem_to_u32(smem);

    const int tid  = threadIdx.x;
    const int lane = tid & 31;
    const int wid  = tid >> 5;
    const int wm   = wid >> 2;
    const int wn   = wid & 3;

    const int m0 = blockIdx.y * 128;
    const int n0 = blockIdx.x * 128;
    const int nch = K >> 6;

    const size_t aBase = (size_t)m0 * K;
    const size_t bBase = (size_t)n0 * K;

    float acc[4][4][4];
    #pragma unroll
    for (int i = 0; i < 4; i++)
        #pragma unroll
        for (int j = 0; j < 4; j++)
            #pragma unroll
            for (int t = 0; t < 4; t++) acc[i][j][t] = 0.0f;

    auto load_chunk = [&](int buf, int k0) {
        const uint32_t tb = sb + buf * TG_STAGE;
        #pragma unroll
        for (int ii = 0; ii < 4; ii++) {
            const int i = tid + ii * 256;
            const int r = i >> 3;
            const int c = i & 7;
            const uint32_t so = (uint32_t)(r * TG_STRIDE + c * 16);
            const size_t aOff = aBase + (size_t)r * K + k0 + c * 8;
            const size_t bOff = bBase + (size_t)r * K + k0 + c * 8;
            CP_ASYNC16(tb + 0 * TG_TILE + so, (const char*)(Ah + aOff));
            CP_ASYNC16(tb + 1 * TG_TILE + so, (const char*)(Al + aOff));
            CP_ASYNC16(tb + 2 * TG_TILE + so, (const char*)(Bh + bOff));
            CP_ASYNC16(tb + 3 * TG_TILE + so, (const char*)(Bl + bOff));
        }
        CP_ASYNC_COMMIT();
    };

    const uint32_t aOffL = (uint32_t)((wm * 64 + (lane & 15)) * TG_STRIDE
                                      + ((lane >> 4) * 8) * 2);
    const uint32_t bOffL = (uint32_t)((wn * 32 + (lane & 7) + ((lane >> 4) & 1) * 8) * TG_STRIDE
                                      + (((lane >> 3) & 1) * 8) * 2);

    load_chunk(0, 0);
    load_chunk(1, 64);

    for (int c = 0; c < nch; c++) {
        const int buf = c & 1;
        if (c + 1 < nch) { CP_ASYNC_WAIT(1); } else { CP_ASYNC_WAIT(0); }
        __syncthreads();

        const uint32_t tb  = sb + buf * TG_STAGE;
        const uint32_t tAh = tb + 0 * TG_TILE + aOffL;
        const uint32_t tAl = tb + 1 * TG_TILE + aOffL;
        const uint32_t tBh = tb + 2 * TG_TILE + bOffL;
        const uint32_t tBl = tb + 3 * TG_TILE + bOffL;

        #pragma unroll
        for (int ks = 0; ks < 4; ks++) {
            const uint32_t ko = ks * 32;
            uint32_t ah[4][4], al[4][4], bh[2][4], bl[2][4];
            #pragma unroll
            for (int mt = 0; mt < 4; mt++) {
                ldsm4(ah[mt], tAh + mt * (16 * TG_STRIDE) + ko);
                ldsm4(al[mt], tAl + mt * (16 * TG_STRIDE) + ko);
            }
            #pragma unroll
            for (int nt = 0; nt < 2; nt++) {
                ldsm4(bh[nt], tBh + nt * (16 * TG_STRIDE) + ko);
                ldsm4(bl[nt], tBl + nt * (16 * TG_STRIDE) + ko);
            }
            #pragma unroll
            for (int mi = 0; mi < 4; mi++)
                #pragma unroll
                for (int ni = 0; ni < 4; ni++) {
                    const int g = ni >> 1, o = (ni & 1) * 2;
                    mma16816(acc[mi][ni], ah[mi], bh[g][o], bh[g][o + 1]);
                    mma16816(acc[mi][ni], al[mi], bh[g][o], bh[g][o + 1]);
                    mma16816(acc[mi][ni], ah[mi], bl[g][o], bl[g][o + 1]);
                }
        }
        __syncthreads();
        if (c + 2 < nch) load_chunk(buf, (c + 2) * 64);
    }

    const int gid = lane >> 2;
    const int tig = lane & 3;

    auto storePair = [&](int m, int n, float v0, float v1) {
        if (bias) { v0 += bias[n]; v1 += bias[n + 1]; }
        if (mode == 0) {
            float2 t; t.x = v0; t.y = v1;
            *reinterpret_cast<float2*>(&outF[(size_t)m * 2048 + n]) = t;
        } else {
            __nv_bfloat16 h0 = __float2bfloat16(v0);
            __nv_bfloat16 l0 = __float2bfloat16(v0 - __bfloat162float(h0));
            __nv_bfloat16 h1 = __float2bfloat16(v1);
            __nv_bfloat16 l1 = __float2bfloat16(v1 - __bfloat162float(h1));
            const int b = m >> 11, s = m & (SSEQ - 1);
            const int h = n >> 7,  d = n & (HDIM - 1);
            const size_t idx = (((size_t)(b * NHEAD + h) * SSEQ) + s) * HDIM + d;
            __nv_bfloat162 th; th.x = h0; th.y = h1;
            __nv_bfloat162 tl; tl.x = l0; tl.y = l1;
            *reinterpret_cast<__nv_bfloat162*>(&outH[idx]) = th;
            *reinterpret_cast<__nv_bfloat162*>(&outL[idx]) = tl;
        }
    };

    #pragma unroll
    for (int mi = 0; mi < 4; mi++) {
        #pragma unroll
        for (int ni = 0; ni < 4; ni++) {
            const int m = m0 + wm * 64 + mi * 16 + gid;
            const int n = n0 + wn * 32 + ni * 8 + tig * 2;
            storePair(m,     n, acc[mi][ni][0], acc[mi][ni][1]);
            storePair(m + 8, n, acc[mi][ni][2], acc[mi][ni][3]);
        }
    }
}

// ===================== fused flash attention (bf16x3) =======================
// Per CTA: head z = blockIdx.y, q-tile q0 = blockIdx.x*128.  8 warps x 16 q-rows.
// 32 kv iterations of 64 keys; online softmax; O accum fp32 in registers.
#define FA_STRIDE  272                       // 128 bf16 + 8 pad
#define FA_QTILE   (128 * FA_STRIDE)         // 34816
#define FA_KVTILE  (64 * FA_STRIDE)          // 17408
#define FA_STAGE   (4 * FA_KVTILE)           // Kh,Kl,Vh,Vl = 69632
#define FA_SMEM    (2 * FA_QTILE + 2 * FA_STAGE)   // 208896

__global__ void __launch_bounds__(256, 1)
fa_kernel(const __nv_bfloat16* __restrict__ qh, const __nv_bfloat16* __restrict__ ql,
          const __nv_bfloat16* __restrict__ kh, const __nv_bfloat16* __restrict__ kl,
          const __nv_bfloat16* __restrict__ vh, const __nv_bfloat16* __restrict__ vl,
          const float* __restrict__ mask,
          __nv_bfloat16* __restrict__ aoh, __nv_bfloat16* __restrict__ aol)
{
    extern __shared__ __align__(128) char smem[];
    const uint32_t sb   = smem_to_u32(smem);
    const uint32_t sQh  = sb;
    const uint32_t sQl  = sb + FA_QTILE;
    const uint32_t sStg = sb + 2 * FA_QTILE;

    const int tid  = threadIdx.x;
    const int lane = tid & 31;
    const int wid  = tid >> 5;
    const int gid  = lane >> 2;
    const int tig  = lane & 3;

    const int z  = blockIdx.y;
    const int q0 = blockIdx.x * 128;
    const int b  = z >> 4;
    const int h  = z & (NHEAD - 1);

    const size_t qBase  = ((size_t)z * SSEQ + q0) * HDIM;
    const size_t kvBase = (size_t)z * SSEQ * HDIM;

    // ---- Q tile load (resident all kernel)
    #pragma unroll
    for (int ii = 0; ii < 8; ii++) {
        const int i = tid + ii * 256;            // 0..2047
        const int r = i >> 4;                    // 0..127
        const int c = i & 15;                    // 16B chunk
        const uint32_t so = (uint32_t)(r * FA_STRIDE + c * 16);
        const size_t go = qBase + (size_t)r * HDIM + c * 8;
        CP_ASYNC16(sQh + so, (const char*)(qh + go));
        CP_ASYNC16(sQl + so, (const char*)(ql + go));
    }
    CP_ASYNC_COMMIT();

    auto load_stage = [&](int st, int k0) {
        const uint32_t tb = sStg + st * FA_STAGE;
        #pragma unroll
        for (int ii = 0; ii < 4; ii++) {
            const int i = tid + ii * 256;        // 0..1023
            const int r = i >> 4;                // 0..63
            const int c = i & 15;
            const uint32_t so = (uint32_t)(r * FA_STRIDE + c * 16);
            const size_t go = kvBase + (size_t)(k0 + r) * HDIM + c * 8;
            CP_ASYNC16(tb + 0 * FA_KVTILE + so, (const char*)(kh + go));
            CP_ASYNC16(tb + 1 * FA_KVTILE + so, (const char*)(kl + go));
            CP_ASYNC16(tb + 2 * FA_KVTILE + so, (const char*)(vh + go));
            CP_ASYNC16(tb + 3 * FA_KVTILE + so, (const char*)(vl + go));
        }
        CP_ASYNC_COMMIT();
    };
    load_stage(0, 0);
    load_stage(1, 64);

    float O[16][4];
    #pragma unroll
    for (int i = 0; i < 16; i++)
        #pragma unroll
        for (int j = 0; j < 4; j++) O[i][j] = 0.0f;
    float m0 = -1e30f, m1 = -1e30f, l0 = 0.0f, l1 = 0.0f;

    const uint32_t aOff = (uint32_t)((16 * wid + (lane & 15)) * FA_STRIDE + (lane >> 4) * 16);
    const uint32_t bOff = (uint32_t)(((lane & 7) + ((lane >> 4) & 1) * 8) * FA_STRIDE
                                     + ((lane >> 3) & 1) * 16);
    const uint32_t vOff = (uint32_t)(((lane & 7) + ((lane >> 3) & 1) * 8) * FA_STRIDE
                                     + ((lane >> 4) & 1) * 16);
    const float* mrow = mask + (size_t)b * SSEQ;
    const float scale = 0.08838834764831845f;   // 1/sqrt(128)

    for (int c = 0; c < 32; c++) {
        if (c + 1 < 32) { CP_ASYNC_WAIT(1); } else { CP_ASYNC_WAIT(0); }
        __syncthreads();
        const uint32_t tb = sStg + (c & 1) * FA_STAGE;
        const int k0 = c * 64;

        // ---- scores S[16 x 64]
        float S[8][4];
        #pragma unroll
        for (int i = 0; i < 8; i++)
            #pragma unroll
            for (int j = 0; j < 4; j++) S[i][j] = 0.0f;

        #pragma unroll
        for (int kd = 0; kd < 8; kd++) {
            uint32_t aH[4], aL[4];
            ldsm4(aH, sQh + aOff + kd * 32);
            ldsm4(aL, sQl + aOff + kd * 32);
            #pragma unroll
            for (int np = 0; np < 4; np++) {
                uint32_t bH[4], bL[4];
                ldsm4(bH, tb + 0 * FA_KVTILE + bOff + np * (16 * FA_STRIDE) + kd * 32);
                ldsm4(bL, tb + 1 * FA_KVTILE + bOff + np * (16 * FA_STRIDE) + kd * 32);
                mma16816(S[2 * np],     aH, bH[0], bH[1]);
                mma16816(S[2 * np],     aL, bH[0], bH[1]);
                mma16816(S[2 * np],     aH, bL[0], bL[1]);
                mma16816(S[2 * np + 1], aH, bH[2], bH[3]);
                mma16816(S[2 * np + 1], aL, bH[2], bH[3]);
                mma16816(S[2 * np + 1], aH, bL[2], bL[3]);
            }
        }

        // ---- scale + mask
        #pragma unroll
        for (int nt = 0; nt < 8; nt++) {
            const float2 mv = *reinterpret_cast<const float2*>(mrow + k0 + nt * 8 + 2 * tig);
            S[nt][0] = fmaf(S[nt][0], scale, mv.x);
            S[nt][1] = fmaf(S[nt][1], scale, mv.y);
            S[nt][2] = fmaf(S[nt][2], scale, mv.x);
            S[nt][3] = fmaf(S[nt][3], scale, mv.y);
        }

        // ---- online softmax
        float mx0 = -1e30f, mx1 = -1e30f;
        #pragma unroll
        for (int nt = 0; nt < 8; nt++) {
            mx0 = fmaxf(mx0, fmaxf(S[nt][0], S[nt][1]));
            mx1 = fmaxf(mx1, fmaxf(S[nt][2], S[nt][3]));
        }
        mx0 = fmaxf(mx0, __shfl_xor_sync(0xFFFFFFFFu, mx0, 1));
        mx0 = fmaxf(mx0, __shfl_xor_sync(0xFFFFFFFFu, mx0, 2));
        mx1 = fmaxf(mx1, __shfl_xor_sync(0xFFFFFFFFu, mx1, 1));
        mx1 = fmaxf(mx1, __shfl_xor_sync(0xFFFFFFFFu, mx1, 2));

        const float nm0 = fmaxf(m0, mx0);
        const float nm1 = fmaxf(m1, mx1);
        const float ef0 = __expf(m0 - nm0);
        const float ef1 = __expf(m1 - nm1);

        float rs0 = 0.0f, rs1 = 0.0f;
        #pragma unroll
        for (int nt = 0; nt < 8; nt++) {
            S[nt][0] = __expf(S[nt][0] - nm0);
            S[nt][1] = __expf(S[nt][1] - nm0);
            S[nt][2] = __expf(S[nt][2] - nm1);
            S[nt][3] = __expf(S[nt][3] - nm1);
            rs0 += S[nt][0] + S[nt][1];
            rs1 += S[nt][2] + S[nt][3];
        }
        rs0 += __shfl_xor_sync(0xFFFFFFFFu, rs0, 1);
        rs0 += __shfl_xor_sync(0xFFFFFFFFu, rs0, 2);
        rs1 += __shfl_xor_sync(0xFFFFFFFFu, rs1, 1);
        rs1 += __shfl_xor_sync(0xFFFFFFFFu, rs1, 2);

        l0 = l0 * ef0 + rs0;
        l1 = l1 * ef1 + rs1;
        m0 = nm0; m1 = nm1;

        #pragma unroll
        for (int nt = 0; nt < 16; nt++) {
            O[nt][0] *= ef0; O[nt][1] *= ef0;
            O[nt][2] *= ef1; O[nt][3] *= ef1;
        }

        // ---- P (hi/lo) @ V  (V via ldmatrix.trans)
        #pragma unroll
        for (int ks = 0; ks < 4; ks++) {
            uint32_t paH[4], paL[4];
            #pragma unroll
            for (int q = 0; q < 2; q++) {      // n-tile 2ks+q
                const float* s4 = S[2 * ks + q];
                #pragma unroll
                for (int rr = 0; rr < 2; rr++) {
                    const float x = s4[rr * 2 + 0];
                    const float y = s4[rr * 2 + 1];
                    const __nv_bfloat16 hx = __float2bfloat16(x);
                    const __nv_bfloat16 hy = __float2bfloat16(y);
                    __nv_bfloat162 th; th.x = hx; th.y = hy;
                    __nv_bfloat162 tl;
                    tl.x = __float2bfloat16(x - __bfloat162float(hx));
                    tl.y = __float2bfloat16(y - __bfloat162float(hy));
                    paH[q * 2 + rr] = *reinterpret_cast<uint32_t*>(&th);
                    paL[q * 2 + rr] = *reinterpret_cast<uint32_t*>(&tl);
                }
            }
            #pragma unroll
            for (int ntp = 0; ntp < 8; ntp++) {
                uint32_t vH[4], vL[4];
                ldsm4t(vH, tb + 2 * FA_KVTILE + vOff + ks * (16 * FA_STRIDE) + ntp * 32);
                ldsm4t(vL, tb + 3 * FA_KVTILE + vOff + ks * (16 * FA_STRIDE) + ntp * 32);
                mma16816(O[2 * ntp],     paH, vH[0], vH[1]);
                mma16816(O[2 * ntp],     paL, vH[0], vH[1]);
                mma16816(O[2 * ntp],     paH, vL[0], vL[1]);
                mma16816(O[2 * ntp + 1], paH, vH[2], vH[3]);
                mma16816(O[2 * ntp + 1], paL, vH[2], vH[3]);
                mma16816(O[2 * ntp + 1], paH, vL[2], vL[3]);
            }
        }

        __syncthreads();
        if (c + 2 < 32) load_stage(c & 1, (c + 2) * 64);
    }

    // ---- epilogue: O /= l, write AO hi/lo bf16 into [B,S,HIDDEN]
    const float inv0 = 1.0f / l0;
    const float inv1 = 1.0f / l1;
    const int r0 = q0 + 16 * wid + gid;
    const int r1 = r0 + 8;
    #pragma unroll
    for (int nt = 0; nt < 16; nt++) {
        const int d = h * HDIM + nt * 8 + 2 * tig;
        const size_t i0 = ((size_t)b * SSEQ + r0) * HIDDEN + d;
        const size_t i1 = ((size_t)b * SSEQ + r1) * HIDDEN + d;
        const float v00 = O[nt][0] * inv0, v01 = O[nt][1] * inv0;
        const float v10 = O[nt][2] * inv1, v11 = O[nt][3] * inv1;

        const __nv_bfloat16 h00 = __float2bfloat16(v00);
        const __nv_bfloat16 h01 = __float2bfloat16(v01);
        const __nv_bfloat16 h10 = __float2bfloat16(v10);
        const __nv_bfloat16 h11 = __float2bfloat16(v11);
        __nv_bfloat162 th0; th0.x = h00; th0.y = h01;
        __nv_bfloat162 th1; th1.x = h10; th1.y = h11;
        __nv_bfloat162 tl0;
        tl0.x = __float2bfloat16(v00 - __bfloat162float(h00));
        tl0.y = __float2bfloat16(v01 - __bfloat162float(h01));
        __nv_bfloat162 tl1;
        tl1.x = __float2bfloat16(v10 - __bfloat162float(h10));
        tl1.y = __float2bfloat16(v11 - __bfloat162float(h11));
        *reinterpret_cast<__nv_bfloat162*>(&aoh[i0]) = th0;
        *reinterpret_cast<__nv_bfloat162*>(&aol[i0]) = tl0;
        *reinterpret_cast<__nv_bfloat162*>(&aoh[i1]) = th1;
        *reinterpret_cast<__nv_bfloat162*>(&aol[i1]) = tl1;
    }
}

// ===================== fp32 -> bf16 hi/lo split =============================
__global__ void __launch_bounds__(256)
split_bf16(const float* __restrict__ in, __nv_bfloat16* __restrict__ hi,
           __nv_bfloat16* __restrict__ lo, int n4)
{
    const int i = blockIdx.x * 256 + threadIdx.x;
    if (i >= n4) return;
    const float4 v = reinterpret_cast<const float4*>(in)[i];
    union { __nv_bfloat16 b[4]; uint2 u; } H, L;
    H.b[0] = __float2bfloat16(v.x);
    H.b[1] = __float2bfloat16(v.y);
    H.b[2] = __float2bfloat16(v.z);
    H.b[3] = __float2bfloat16(v.w);
    L.b[0] = __float2bfloat16(v.x - __bfloat162float(H.b[0]));
    L.b[1] = __float2bfloat16(v.y - __bfloat162float(H.b[1]));
    L.b[2] = __float2bfloat16(v.z - __bfloat162float(H.b[2]));
    L.b[3] = __float2bfloat16(v.w - __bfloat162float(H.b[3]));
    reinterpret_cast<uint2*>(hi)[i] = H.u;
    reinterpret_cast<uint2*>(lo)[i] = L.u;
}

// ---------------------------------------------------------------------------
extern "C" void kernel_launch(void* const* d_in, const int* in_sizes, int n_in,
                              void* d_out, int out_size)
{
    (void)in_sizes; (void)n_in; (void)out_size;
    const float* x    = (const float*)d_in[0];
    const float* mask = (const float*)d_in[1];
    const float* Wq   = (const float*)d_in[2];
    const float* bq   = (const float*)d_in[3];
    const float* Wk   = (const float*)d_in[4];
    const float* bk   = (const float*)d_in[5];
    const float* Wv   = (const float*)d_in[6];
    const float* bv   = (const float*)d_in[7];
    const float* Wo   = (const float*)d_in[8];
    const float* bo   = (const float*)d_in[9];
    float* out = (float*)d_out;

    __nv_bfloat16 *xh, *xl, *wqh, *wql, *wkh, *wkl, *wvh, *wvl, *woh, *wol;
    __nv_bfloat16 *qh, *ql, *kh, *kl, *vh, *vl, *aoh, *aol;
    cudaGetSymbolAddress((void**)&xh,  g_xh);
    cudaGetSymbolAddress((void**)&xl,  g_xl);
    cudaGetSymbolAddress((void**)&wqh, g_wqh);
    cudaGetSymbolAddress((void**)&wql, g_wql);
    cudaGetSymbolAddress((void**)&wkh, g_wkh);
    cudaGetSymbolAddress((void**)&wkl, g_wkl);
    cudaGetSymbolAddress((void**)&wvh, g_wvh);
    cudaGetSymbolAddress((void**)&wvl, g_wvl);
    cudaGetSymbolAddress((void**)&woh, g_woh);
    cudaGetSymbolAddress((void**)&wol, g_wol);
    cudaGetSymbolAddress((void**)&qh,  g_qh);
    cudaGetSymbolAddress((void**)&ql,  g_ql);
    cudaGetSymbolAddress((void**)&kh,  g_kh);
    cudaGetSymbolAddress((void**)&kl,  g_kl);
    cudaGetSymbolAddress((void**)&vh,  g_vh);
    cudaGetSymbolAddress((void**)&vl,  g_vl);
    cudaGetSymbolAddress((void**)&aoh, g_aoh);
    cudaGetSymbolAddress((void**)&aol, g_aol);

    cudaFuncSetAttribute(tgemm_nt, cudaFuncAttributeMaxDynamicSharedMemorySize,
                         TG_SMEM);
    cudaFuncSetAttribute(fa_kernel, cudaFuncAttributeMaxDynamicSharedMemorySize,
                         FA_SMEM);

    // ---- hi/lo splits
    const int nX4 = (MROWS * HIDDEN) / 4;
    const int nW4 = (HIDDEN * HIDDEN) / 4;
    split_bf16<<<nX4 / 256, 256>>>(x,  xh,  xl,  nX4);
    split_bf16<<<nW4 / 256, 256>>>(Wq, wqh, wql, nW4);
    split_bf16<<<nW4 / 256, 256>>>(Wk, wkh, wkl, nW4);
    split_bf16<<<nW4 / 256, 256>>>(Wv, wvh, wvl, nW4);
    split_bf16<<<nW4 / 256, 256>>>(Wo, woh, wol, nW4);

    // ---- QKV projections -> bf16 hi/lo [B,H,S,D]
    const dim3 gProj(HIDDEN / 128, MROWS / 128, 1);
    tgemm_nt<<<gProj, 256, TG_SMEM>>>(xh, xl, wqh, wql, bq, HIDDEN, 1, nullptr, qh, ql);
    tgemm_nt<<<gProj, 256, TG_SMEM>>>(xh, xl, wkh, wkl, bk, HIDDEN, 1, nullptr, kh, kl);
    tgemm_nt<<<gProj, 256, TG_SMEM>>>(xh, xl, wvh, wvl, bv, HIDDEN, 1, nullptr, vh, vl);

    // ---- fused attention -> AO bf16 hi/lo [B,S,HIDDEN]
    const dim3 gFA(SSEQ / 128, BH, 1);   // (16, 32)
    fa_kernel<<<gFA, 256, FA_SMEM>>>(qh, ql, kh, kl, vh, vl, mask, aoh, aol);

    // ---- output projection (+bias) -> d_out
    tgemm_nt<<<gProj, 256, TG_SMEM>>>(aoh, aol, woh, wol, bo, HIDDEN, 0,
                                      out, nullptr, nullptr);
}

// round 5
// speedup vs baseline: 3.0988x; 1.0340x over previous
#include <cuda_runtime.h>
#include <cuda_bf16.h>
#include <math.h>
#include <stdint.h>

// Problem constants
#define HIDDEN 2048
#define NHEAD  16
#define HDIM   128
#define BB     2
#define SSEQ   2048
#define BH     (BB * NHEAD)      // 32
#define MROWS  (BB * SSEQ)       // 4096

// ---------------- scratch (device globals; no allocation allowed) -----------
__device__ __align__(128) __nv_bfloat16 g_xh [(size_t)MROWS * HIDDEN];
__device__ __align__(128) __nv_bfloat16 g_xl [(size_t)MROWS * HIDDEN];
__device__ __align__(128) __nv_bfloat16 g_w3h[(size_t)3 * HIDDEN * HIDDEN];  // Wq|Wk|Wv
__device__ __align__(128) __nv_bfloat16 g_w3l[(size_t)3 * HIDDEN * HIDDEN];
__device__ __align__(128) __nv_bfloat16 g_woh[(size_t)HIDDEN * HIDDEN];
__device__ __align__(128) __nv_bfloat16 g_wol[(size_t)HIDDEN * HIDDEN];
__device__ __align__(128) float         g_b3 [3 * HIDDEN];                   // bq|bk|bv
__device__ __align__(128) __nv_bfloat16 g_qh [(size_t)BH * SSEQ * HDIM];  // [B,H,S,D]
__device__ __align__(128) __nv_bfloat16 g_ql [(size_t)BH * SSEQ * HDIM];
__device__ __align__(128) __nv_bfloat16 g_kh [(size_t)BH * SSEQ * HDIM];
__device__ __align__(128) __nv_bfloat16 g_kl [(size_t)BH * SSEQ * HDIM];
__device__ __align__(128) __nv_bfloat16 g_vh [(size_t)BH * SSEQ * HDIM];
__device__ __align__(128) __nv_bfloat16 g_vl [(size_t)BH * SSEQ * HDIM];
__device__ __align__(128) __nv_bfloat16 g_aoh[(size_t)MROWS * HIDDEN];
__device__ __align__(128) __nv_bfloat16 g_aol[(size_t)MROWS * HIDDEN];

// ============================ PTX helpers ====================================
__device__ __forceinline__ uint32_t smem_to_u32(const void* smem_ptr) {
    uint32_t addr;
    asm("{ .reg .u64 tmp; cvta.to.shared.u64 tmp, %1; cvt.u32.u64 %0, tmp; }"
        : "=r"(addr) : "l"(smem_ptr));
    return addr;
}
#define CP_ASYNC16(smem_u32, gptr) \
    asm volatile("cp.async.cg.shared.global [%0], [%1], 16;" \
        :: "r"((uint32_t)(smem_u32)), "l"(gptr) : "memory")
#define CP_ASYNC_COMMIT() asm volatile("cp.async.commit_group;" ::: "memory")
#define CP_ASYNC_WAIT(n)  asm volatile("cp.async.wait_group %0;" :: "n"(n) : "memory")

__device__ __forceinline__ void ldsm4(uint32_t* r, uint32_t addr) {
    asm volatile("ldmatrix.sync.aligned.m8n8.x4.shared.b16 {%0,%1,%2,%3}, [%4];"
        : "=r"(r[0]), "=r"(r[1]), "=r"(r[2]), "=r"(r[3]) : "r"(addr));
}
__device__ __forceinline__ void ldsm4t(uint32_t* r, uint32_t addr) {
    asm volatile("ldmatrix.sync.aligned.m8n8.x4.trans.shared.b16 {%0,%1,%2,%3}, [%4];"
        : "=r"(r[0]), "=r"(r[1]), "=r"(r[2]), "=r"(r[3]) : "r"(addr));
}
__device__ __forceinline__ void mma16816(float* d, const uint32_t* a,
                                         uint32_t b0, uint32_t b1) {
    asm volatile(
        "mma.sync.aligned.m16n8k16.row.col.f32.bf16.bf16.f32 "
        "{%0,%1,%2,%3}, {%4,%5,%6,%7}, {%8,%9}, {%0,%1,%2,%3};"
        : "+f"(d[0]), "+f"(d[1]), "+f"(d[2]), "+f"(d[3])
        : "r"(a[0]), "r"(a[1]), "r"(a[2]), "r"(a[3]), "r"(b0), "r"(b1));
}

// ===================== HMMA bf16x3 NT GEMM ==================================
// C = (Ah+Al) @ (Bh+Bl)^T (+bias).  A*: [M,K] bf16 row-major, B*: [Ntot,K].
// CTA tile 128x128, warp 64x32, K-chunk 64, 3-stage cp.async pipeline.
// Kept products: AhBh + AlBh + AhBl.
// mode 0: fp32 C[m*Ntot+n] -> outF
// mode 1: fused-QKV bf16 hi/lo scatter; p = n>>11 selects (q,k,v) arrays,
//         layout [B,H,S,D].
#define TG_STRIDE   144
#define TG_TILE     (128 * TG_STRIDE)
#define TG_STAGE    (4 * TG_TILE)          // Ah, Al, Bh, Bl = 73728
#define TG_SMEM     (3 * TG_STAGE)         // 221184

__global__ void __launch_bounds__(256, 1)
tgemm_nt(const __nv_bfloat16* __restrict__ Ah, const __nv_bfloat16* __restrict__ Al,
         const __nv_bfloat16* __restrict__ Bh, const __nv_bfloat16* __restrict__ Bl,
         const float* __restrict__ bias, int K, int Ntot, int mode,
         float* __restrict__ outF,
         __nv_bfloat16* __restrict__ o0h, __nv_bfloat16* __restrict__ o0l,
         __nv_bfloat16* __restrict__ o1h, __nv_bfloat16* __restrict__ o1l,
         __nv_bfloat16* __restrict__ o2h, __nv_bfloat16* __restrict__ o2l)
{
    extern __shared__ __align__(128) char smem[];
    const uint32_t sb = smem_to_u32(smem);

    const int tid  = threadIdx.x;
    const int lane = tid & 31;
    const int wid  = tid >> 5;
    const int wm   = wid >> 2;
    const int wn   = wid & 3;

    const int m0 = blockIdx.y * 128;
    const int n0 = blockIdx.x * 128;
    const int nch = K >> 6;

    const size_t aBase = (size_t)m0 * K;
    const size_t bBase = (size_t)n0 * K;

    float acc[4][4][4];
    #pragma unroll
    for (int i = 0; i < 4; i++)
        #pragma unroll
        for (int j = 0; j < 4; j++)
            #pragma unroll
            for (int t = 0; t < 4; t++) acc[i][j][t] = 0.0f;

    auto load_chunk = [&](int buf, int k0) {
        const uint32_t tb = sb + buf * TG_STAGE;
        #pragma unroll
        for (int ii = 0; ii < 4; ii++) {
            const int i = tid + ii * 256;
            const int r = i >> 3;
            const int c = i & 7;
            const uint32_t so = (uint32_t)(r * TG_STRIDE + c * 16);
            const size_t aOff = aBase + (size_t)r * K + k0 + c * 8;
            const size_t bOff = bBase + (size_t)r * K + k0 + c * 8;
            CP_ASYNC16(tb + 0 * TG_TILE + so, (const char*)(Ah + aOff));
            CP_ASYNC16(tb + 1 * TG_TILE + so, (const char*)(Al + aOff));
            CP_ASYNC16(tb + 2 * TG_TILE + so, (const char*)(Bh + bOff));
            CP_ASYNC16(tb + 3 * TG_TILE + so, (const char*)(Bl + bOff));
        }
        CP_ASYNC_COMMIT();
    };

    const uint32_t aOffL = (uint32_t)((wm * 64 + (lane & 15)) * TG_STRIDE
                                      + ((lane >> 4) * 8) * 2);
    const uint32_t bOffL = (uint32_t)((wn * 32 + (lane & 7) + ((lane >> 4) & 1) * 8) * TG_STRIDE
                                      + (((lane >> 3) & 1) * 8) * 2);

    // prologue: fill 3 stages
    load_chunk(0, 0);
    if (nch > 1) load_chunk(1, 64);
    if (nch > 2) load_chunk(2, 128);

    for (int c = 0; c < nch; c++) {
        const int buf = c % 3;
        if (c + 2 < nch)      { CP_ASYNC_WAIT(2); }
        else if (c + 1 < nch) { CP_ASYNC_WAIT(1); }
        else                  { CP_ASYNC_WAIT(0); }
        __syncthreads();

        const uint32_t tb  = sb + buf * TG_STAGE;
        const uint32_t tAh = tb + 0 * TG_TILE + aOffL;
        const uint32_t tAl = tb + 1 * TG_TILE + aOffL;
        const uint32_t tBh = tb + 2 * TG_TILE + bOffL;
        const uint32_t tBl = tb + 3 * TG_TILE + bOffL;

        #pragma unroll
        for (int ks = 0; ks < 4; ks++) {
            const uint32_t ko = ks * 32;
            uint32_t ah[4][4], al[4][4], bh[2][4], bl[2][4];
            #pragma unroll
            for (int mt = 0; mt < 4; mt++) {
                ldsm4(ah[mt], tAh + mt * (16 * TG_STRIDE) + ko);
                ldsm4(al[mt], tAl + mt * (16 * TG_STRIDE) + ko);
            }
            #pragma unroll
            for (int nt = 0; nt < 2; nt++) {
                ldsm4(bh[nt], tBh + nt * (16 * TG_STRIDE) + ko);
                ldsm4(bl[nt], tBl + nt * (16 * TG_STRIDE) + ko);
            }
            #pragma unroll
            for (int mi = 0; mi < 4; mi++)
                #pragma unroll
                for (int ni = 0; ni < 4; ni++) {
                    const int g = ni >> 1, o = (ni & 1) * 2;
                    mma16816(acc[mi][ni], ah[mi], bh[g][o], bh[g][o + 1]);
                    mma16816(acc[mi][ni], al[mi], bh[g][o], bh[g][o + 1]);
                    mma16816(acc[mi][ni], ah[mi], bl[g][o], bl[g][o + 1]);
                }
        }
        __syncthreads();
        if (c + 3 < nch) load_chunk(buf, (c + 3) * 64);
    }

    const int gid = lane >> 2;
    const int tig = lane & 3;

    auto storePair = [&](int m, int n, float v0, float v1) {
        if (bias) { v0 += bias[n]; v1 += bias[n + 1]; }
        if (mode == 0) {
            float2 t; t.x = v0; t.y = v1;
            *reinterpret_cast<float2*>(&outF[(size_t)m * Ntot + n]) = t;
        } else {
            __nv_bfloat16 h0 = __float2bfloat16(v0);
            __nv_bfloat16 l0 = __float2bfloat16(v0 - __bfloat162float(h0));
            __nv_bfloat16 h1 = __float2bfloat16(v1);
            __nv_bfloat16 l1 = __float2bfloat16(v1 - __bfloat162float(h1));
            const int p  = n >> 11;                 // 0=q, 1=k, 2=v
            const int n2 = n & (HIDDEN - 1);
            const int b = m >> 11, s = m & (SSEQ - 1);
            const int h = n2 >> 7, d = n2 & (HDIM - 1);
            __nv_bfloat16* oh = (p == 0) ? o0h : ((p == 1) ? o1h : o2h);
            __nv_bfloat16* ol = (p == 0) ? o0l : ((p == 1) ? o1l : o2l);
            const size_t idx = (((size_t)(b * NHEAD + h) * SSEQ) + s) * HDIM + d;
            __nv_bfloat162 th; th.x = h0; th.y = h1;
            __nv_bfloat162 tl; tl.x = l0; tl.y = l1;
            *reinterpret_cast<__nv_bfloat162*>(&oh[idx]) = th;
            *reinterpret_cast<__nv_bfloat162*>(&ol[idx]) = tl;
        }
    };

    #pragma unroll
    for (int mi = 0; mi < 4; mi++) {
        #pragma unroll
        for (int ni = 0; ni < 4; ni++) {
            const int m = m0 + wm * 64 + mi * 16 + gid;
            const int n = n0 + wn * 32 + ni * 8 + tig * 2;
            storePair(m,     n, acc[mi][ni][0], acc[mi][ni][1]);
            storePair(m + 8, n, acc[mi][ni][2], acc[mi][ni][3]);
        }
    }
}

// ===================== fused flash attention (bf16x3) =======================
#define FA_STRIDE  272                       // 128 bf16 + 8 pad
#define FA_QTILE   (128 * FA_STRIDE)         // 34816
#define FA_KVTILE  (64 * FA_STRIDE)          // 17408
#define FA_STAGE   (4 * FA_KVTILE)           // Kh,Kl,Vh,Vl = 69632
#define FA_SMEM    (2 * FA_QTILE + 2 * FA_STAGE)   // 208896

__global__ void __launch_bounds__(256, 1)
fa_kernel(const __nv_bfloat16* __restrict__ qh, const __nv_bfloat16* __restrict__ ql,
          const __nv_bfloat16* __restrict__ kh, const __nv_bfloat16* __restrict__ kl,
          const __nv_bfloat16* __restrict__ vh, const __nv_bfloat16* __restrict__ vl,
          const float* __restrict__ mask,
          __nv_bfloat16* __restrict__ aoh, __nv_bfloat16* __restrict__ aol)
{
    extern __shared__ __align__(128) char smem[];
    const uint32_t sb   = smem_to_u32(smem);
    const uint32_t sQh  = sb;
    const uint32_t sQl  = sb + FA_QTILE;
    const uint32_t sStg = sb + 2 * FA_QTILE;

    const int tid  = threadIdx.x;
    const int lane = tid & 31;
    const int wid  = tid >> 5;
    const int gid  = lane >> 2;
    const int tig  = lane & 3;

    const int z  = blockIdx.y;
    const int q0 = blockIdx.x * 128;
    const int b  = z >> 4;
    const int h  = z & (NHEAD - 1);

    const size_t qBase  = ((size_t)z * SSEQ + q0) * HDIM;
    const size_t kvBase = (size_t)z * SSEQ * HDIM;

    #pragma unroll
    for (int ii = 0; ii < 8; ii++) {
        const int i = tid + ii * 256;
        const int r = i >> 4;
        const int c = i & 15;
        const uint32_t so = (uint32_t)(r * FA_STRIDE + c * 16);
        const size_t go = qBase + (size_t)r * HDIM + c * 8;
        CP_ASYNC16(sQh + so, (const char*)(qh + go));
        CP_ASYNC16(sQl + so, (const char*)(ql + go));
    }
    CP_ASYNC_COMMIT();

    auto load_stage = [&](int st, int k0) {
        const uint32_t tb = sStg + st * FA_STAGE;
        #pragma unroll
        for (int ii = 0; ii < 4; ii++) {
            const int i = tid + ii * 256;
            const int r = i >> 4;
            const int c = i & 15;
            const uint32_t so = (uint32_t)(r * FA_STRIDE + c * 16);
            const size_t go = kvBase + (size_t)(k0 + r) * HDIM + c * 8;
            CP_ASYNC16(tb + 0 * FA_KVTILE + so, (const char*)(kh + go));
            CP_ASYNC16(tb + 1 * FA_KVTILE + so, (const char*)(kl + go));
            CP_ASYNC16(tb + 2 * FA_KVTILE + so, (const char*)(vh + go));
            CP_ASYNC16(tb + 3 * FA_KVTILE + so, (const char*)(vl + go));
        }
        CP_ASYNC_COMMIT();
    };
    load_stage(0, 0);
    load_stage(1, 64);

    float O[16][4];
    #pragma unroll
    for (int i = 0; i < 16; i++)
        #pragma unroll
        for (int j = 0; j < 4; j++) O[i][j] = 0.0f;
    float m0 = -1e30f, m1 = -1e30f, l0 = 0.0f, l1 = 0.0f;

    const uint32_t aOff = (uint32_t)((16 * wid + (lane & 15)) * FA_STRIDE + (lane >> 4) * 16);
    const uint32_t bOff = (uint32_t)(((lane & 7) + ((lane >> 4) & 1) * 8) * FA_STRIDE
                                     + ((lane >> 3) & 1) * 16);
    const uint32_t vOff = (uint32_t)(((lane & 7) + ((lane >> 3) & 1) * 8) * FA_STRIDE
                                     + ((lane >> 4) & 1) * 16);
    const float* mrow = mask + (size_t)b * SSEQ;
    const float scale = 0.08838834764831845f;   // 1/sqrt(128)

    for (int c = 0; c < 32; c++) {
        if (c + 1 < 32) { CP_ASYNC_WAIT(1); } else { CP_ASYNC_WAIT(0); }
        __syncthreads();
        const uint32_t tb = sStg + (c & 1) * FA_STAGE;
        const int k0 = c * 64;

        float S[8][4];
        #pragma unroll
        for (int i = 0; i < 8; i++)
            #pragma unroll
            for (int j = 0; j < 4; j++) S[i][j] = 0.0f;

        #pragma unroll
        for (int kd = 0; kd < 8; kd++) {
            uint32_t aH[4], aL[4];
            ldsm4(aH, sQh + aOff + kd * 32);
            ldsm4(aL, sQl + aOff + kd * 32);
            #pragma unroll
            for (int np = 0; np < 4; np++) {
                uint32_t bH[4], bL[4];
                ldsm4(bH, tb + 0 * FA_KVTILE + bOff + np * (16 * FA_STRIDE) + kd * 32);
                ldsm4(bL, tb + 1 * FA_KVTILE + bOff + np * (16 * FA_STRIDE) + kd * 32);
                mma16816(S[2 * np],     aH, bH[0], bH[1]);
                mma16816(S[2 * np],     aL, bH[0], bH[1]);
                mma16816(S[2 * np],     aH, bL[0], bL[1]);
                mma16816(S[2 * np + 1], aH, bH[2], bH[3]);
                mma16816(S[2 * np + 1], aL, bH[2], bH[3]);
                mma16816(S[2 * np + 1], aH, bL[2], bL[3]);
            }
        }

        #pragma unroll
        for (int nt = 0; nt < 8; nt++) {
            const float2 mv = *reinterpret_cast<const float2*>(mrow + k0 + nt * 8 + 2 * tig);
            S[nt][0] = fmaf(S[nt][0], scale, mv.x);
            S[nt][1] = fmaf(S[nt][1], scale, mv.y);
            S[nt][2] = fmaf(S[nt][2], scale, mv.x);
            S[nt][3] = fmaf(S[nt][3], scale, mv.y);
        }

        float mx0 = -1e30f, mx1 = -1e30f;
        #pragma unroll
        for (int nt = 0; nt < 8; nt++) {
            mx0 = fmaxf(mx0, fmaxf(S[nt][0], S[nt][1]));
            mx1 = fmaxf(mx1, fmaxf(S[nt][2], S[nt][3]));
        }
        mx0 = fmaxf(mx0, __shfl_xor_sync(0xFFFFFFFFu, mx0, 1));
        mx0 = fmaxf(mx0, __shfl_xor_sync(0xFFFFFFFFu, mx0, 2));
        mx1 = fmaxf(mx1, __shfl_xor_sync(0xFFFFFFFFu, mx1, 1));
        mx1 = fmaxf(mx1, __shfl_xor_sync(0xFFFFFFFFu, mx1, 2));

        const float nm0 = fmaxf(m0, mx0);
        const float nm1 = fmaxf(m1, mx1);
        const float ef0 = __expf(m0 - nm0);
        const float ef1 = __expf(m1 - nm1);

        float rs0 = 0.0f, rs1 = 0.0f;
        #pragma unroll
        for (int nt = 0; nt < 8; nt++) {
            S[nt][0] = __expf(S[nt][0] - nm0);
            S[nt][1] = __expf(S[nt][1] - nm0);
            S[nt][2] = __expf(S[nt][2] - nm1);
            S[nt][3] = __expf(S[nt][3] - nm1);
            rs0 += S[nt][0] + S[nt][1];
            rs1 += S[nt][2] + S[nt][3];
        }
        rs0 += __shfl_xor_sync(0xFFFFFFFFu, rs0, 1);
        rs0 += __shfl_xor_sync(0xFFFFFFFFu, rs0, 2);
        rs1 += __shfl_xor_sync(0xFFFFFFFFu, rs1, 1);
        rs1 += __shfl_xor_sync(0xFFFFFFFFu, rs1, 2);

        l0 = l0 * ef0 + rs0;
        l1 = l1 * ef1 + rs1;
        m0 = nm0; m1 = nm1;

        #pragma unroll
        for (int nt = 0; nt < 16; nt++) {
            O[nt][0] *= ef0; O[nt][1] *= ef0;
            O[nt][2] *= ef1; O[nt][3] *= ef1;
        }

        #pragma unroll
        for (int ks = 0; ks < 4; ks++) {
            uint32_t paH[4], paL[4];
            #pragma unroll
            for (int q = 0; q < 2; q++) {
                const float* s4 = S[2 * ks + q];
                #pragma unroll
                for (int rr = 0; rr < 2; rr++) {
                    const float x = s4[rr * 2 + 0];
                    const float y = s4[rr * 2 + 1];
                    const __nv_bfloat16 hx = __float2bfloat16(x);
                    const __nv_bfloat16 hy = __float2bfloat16(y);
                    __nv_bfloat162 th; th.x = hx; th.y = hy;
                    __nv_bfloat162 tl;
                    tl.x = __float2bfloat16(x - __bfloat162float(hx));
                    tl.y = __float2bfloat16(y - __bfloat162float(hy));
                    paH[q * 2 + rr] = *reinterpret_cast<uint32_t*>(&th);
                    paL[q * 2 + rr] = *reinterpret_cast<uint32_t*>(&tl);
                }
            }
            #pragma unroll
            for (int ntp = 0; ntp < 8; ntp++) {
                uint32_t vH[4], vL[4];
                ldsm4t(vH, tb + 2 * FA_KVTILE + vOff + ks * (16 * FA_STRIDE) + ntp * 32);
                ldsm4t(vL, tb + 3 * FA_KVTILE + vOff + ks * (16 * FA_STRIDE) + ntp * 32);
                mma16816(O[2 * ntp],     paH, vH[0], vH[1]);
                mma16816(O[2 * ntp],     paL, vH[0], vH[1]);
                mma16816(O[2 * ntp],     paH, vL[0], vL[1]);
                mma16816(O[2 * ntp + 1], paH, vH[2], vH[3]);
                mma16816(O[2 * ntp + 1], paL, vH[2], vH[3]);
                mma16816(O[2 * ntp + 1], paH, vL[2], vL[3]);
            }
        }

        __syncthreads();
        if (c + 2 < 32) load_stage(c & 1, (c + 2) * 64);
    }

    const float inv0 = 1.0f / l0;
    const float inv1 = 1.0f / l1;
    const int r0 = q0 + 16 * wid + gid;
    const int r1 = r0 + 8;
    #pragma unroll
    for (int nt = 0; nt < 16; nt++) {
        const int d = h * HDIM + nt * 8 + 2 * tig;
        const size_t i0 = ((size_t)b * SSEQ + r0) * HIDDEN + d;
        const size_t i1 = ((size_t)b * SSEQ + r1) * HIDDEN + d;
        const float v00 = O[nt][0] * inv0, v01 = O[nt][1] * inv0;
        const float v10 = O[nt][2] * inv1, v11 = O[nt][3] * inv1;

        const __nv_bfloat16 h00 = __float2bfloat16(v00);
        const __nv_bfloat16 h01 = __float2bfloat16(v01);
        const __nv_bfloat16 h10 = __float2bfloat16(v10);
        const __nv_bfloat16 h11 = __float2bfloat16(v11);
        __nv_bfloat162 th0; th0.x = h00; th0.y = h01;
        __nv_bfloat162 th1; th1.x = h10; th1.y = h11;
        __nv_bfloat162 tl0;
        tl0.x = __float2bfloat16(v00 - __bfloat162float(h00));
        tl0.y = __float2bfloat16(v01 - __bfloat162float(h01));
        __nv_bfloat162 tl1;
        tl1.x = __float2bfloat16(v10 - __bfloat162float(h10));
        tl1.y = __float2bfloat16(v11 - __bfloat162float(h11));
        *reinterpret_cast<__nv_bfloat162*>(&aoh[i0]) = th0;
        *reinterpret_cast<__nv_bfloat162*>(&aol[i0]) = tl0;
        *reinterpret_cast<__nv_bfloat162*>(&aoh[i1]) = th1;
        *reinterpret_cast<__nv_bfloat162*>(&aol[i1]) = tl1;
    }
}

// ===================== fp32 -> bf16 hi/lo split =============================
__global__ void __launch_bounds__(256)
split_bf16(const float* __restrict__ in, __nv_bfloat16* __restrict__ hi,
           __nv_bfloat16* __restrict__ lo, int n4)
{
    const int i = blockIdx.x * 256 + threadIdx.x;
    if (i >= n4) return;
    const float4 v = reinterpret_cast<const float4*>(in)[i];
    union { __nv_bfloat16 b[4]; uint2 u; } H, L;
    H.b[0] = __float2bfloat16(v.x);
    H.b[1] = __float2bfloat16(v.y);
    H.b[2] = __float2bfloat16(v.z);
    H.b[3] = __float2bfloat16(v.w);
    L.b[0] = __float2bfloat16(v.x - __bfloat162float(H.b[0]));
    L.b[1] = __float2bfloat16(v.y - __bfloat162float(H.b[1]));
    L.b[2] = __float2bfloat16(v.z - __bfloat162float(H.b[2]));
    L.b[3] = __float2bfloat16(v.w - __bfloat162float(H.b[3]));
    reinterpret_cast<uint2*>(hi)[i] = H.u;
    reinterpret_cast<uint2*>(lo)[i] = L.u;
}

// bias concat: [bq | bk | bv]
__global__ void __launch_bounds__(256)
concat_bias(const float* __restrict__ a, const float* __restrict__ b,
            const float* __restrict__ c, float* __restrict__ o)
{
    const int i = blockIdx.x * 256 + threadIdx.x;
    if (i < HIDDEN)          o[i] = a[i];
    else if (i < 2 * HIDDEN) o[i] = b[i - HIDDEN];
    else if (i < 3 * HIDDEN) o[i] = c[i - 2 * HIDDEN];
}

// ---------------------------------------------------------------------------
extern "C" void kernel_launch(void* const* d_in, const int* in_sizes, int n_in,
                              void* d_out, int out_size)
{
    (void)in_sizes; (void)n_in; (void)out_size;
    const float* x    = (const float*)d_in[0];
    const float* mask = (const float*)d_in[1];
    const float* Wq   = (const float*)d_in[2];
    const float* bq   = (const float*)d_in[3];
    const float* Wk   = (const float*)d_in[4];
    const float* bk   = (const float*)d_in[5];
    const float* Wv   = (const float*)d_in[6];
    const float* bv   = (const float*)d_in[7];
    const float* Wo   = (const float*)d_in[8];
    const float* bo   = (const float*)d_in[9];
    float* out = (float*)d_out;

    __nv_bfloat16 *xh, *xl, *w3h, *w3l, *woh, *wol;
    __nv_bfloat16 *qh, *ql, *kh, *kl, *vh, *vl, *aoh, *aol;
    float* b3;
    cudaGetSymbolAddress((void**)&xh,  g_xh);
    cudaGetSymbolAddress((void**)&xl,  g_xl);
    cudaGetSymbolAddress((void**)&w3h, g_w3h);
    cudaGetSymbolAddress((void**)&w3l, g_w3l);
    cudaGetSymbolAddress((void**)&woh, g_woh);
    cudaGetSymbolAddress((void**)&wol, g_wol);
    cudaGetSymbolAddress((void**)&b3,  g_b3);
    cudaGetSymbolAddress((void**)&qh,  g_qh);
    cudaGetSymbolAddress((void**)&ql,  g_ql);
    cudaGetSymbolAddress((void**)&kh,  g_kh);
    cudaGetSymbolAddress((void**)&kl,  g_kl);
    cudaGetSymbolAddress((void**)&vh,  g_vh);
    cudaGetSymbolAddress((void**)&vl,  g_vl);
    cudaGetSymbolAddress((void**)&aoh, g_aoh);
    cudaGetSymbolAddress((void**)&aol, g_aol);

    cudaFuncSetAttribute(tgemm_nt, cudaFuncAttributeMaxDynamicSharedMemorySize,
                         TG_SMEM);
    cudaFuncSetAttribute(fa_kernel, cudaFuncAttributeMaxDynamicSharedMemorySize,
                         FA_SMEM);

    // ---- hi/lo splits (W splits land in the combined QKV weight buffer)
    const int nX4 = (MROWS * HIDDEN) / 4;
    const int nW4 = (HIDDEN * HIDDEN) / 4;
    const size_t wOff = (size_t)HIDDEN * HIDDEN;
    split_bf16<<<nX4 / 256, 256>>>(x,  xh,  xl,  nX4);
    split_bf16<<<nW4 / 256, 256>>>(Wq, w3h,            w3l,            nW4);
    split_bf16<<<nW4 / 256, 256>>>(Wk, w3h + wOff,     w3l + wOff,     nW4);
    split_bf16<<<nW4 / 256, 256>>>(Wv, w3h + 2 * wOff, w3l + 2 * wOff, nW4);
    split_bf16<<<nW4 / 256, 256>>>(Wo, woh, wol, nW4);
    concat_bias<<<(3 * HIDDEN) / 256, 256>>>(bq, bk, bv, b3);

    // ---- fused QKV projection -> bf16 hi/lo [B,H,S,D] x3
    const dim3 gQKV(3 * HIDDEN / 128, MROWS / 128, 1);   // (48, 32)
    tgemm_nt<<<gQKV, 256, TG_SMEM>>>(xh, xl, w3h, w3l, b3, HIDDEN, 3 * HIDDEN, 1,
                                     nullptr, qh, ql, kh, kl, vh, vl);

    // ---- fused attention -> AO bf16 hi/lo [B,S,HIDDEN]
    const dim3 gFA(SSEQ / 128, BH, 1);   // (16, 32)
    fa_kernel<<<gFA, 256, FA_SMEM>>>(qh, ql, kh, kl, vh, vl, mask, aoh, aol);

    // ---- output projection (+bias) -> d_out
    const dim3 gO(HIDDEN / 128, MROWS / 128, 1);
    tgemm_nt<<<gO, 256, TG_SMEM>>>(aoh, aol, woh, wol, bo, HIDDEN, HIDDEN, 0,
                                   out, nullptr, nullptr, nullptr, nullptr,
                                   nullptr, nullptr);
}